// round 1
// baseline (speedup 1.0000x reference)
#include <cuda_runtime.h>

#define T_DIM 4096
#define B_DIM 64
#define F_DIM 64
#define CS    128              // output chunk size (T_DIM / NC)
#define WU    256              // warm-up steps (om^256 ~ 1.2e-9)
#define NC    (T_DIM / CS)     // 32 chunks
#define LAG   25
#define NTOT  ((size_t)B_DIM * T_DIM * F_DIM)   // 16777216

#define ALPHA (2.0f / 26.0f)
#define OM    (24.0f / 26.0f)

__device__ __forceinline__ void estep(float4& e, const float4 xv, int t) {
    // e = (alpha * x_t + om * e_prev) / max(1 - om^(t+1), 1e-10)
    e.x = fmaf(OM, e.x, ALPHA * xv.x);
    e.y = fmaf(OM, e.y, ALPHA * xv.y);
    e.z = fmaf(OM, e.z, ALPHA * xv.z);
    e.w = fmaf(OM, e.w, ALPHA * xv.w);
    if (t < 192) {             // for t >= 166, om^(t+1) underflows below fp32 ulp of 1
        float w  = 1.0f - __powf(OM, (float)(t + 1));
        float iw = 1.0f / fmaxf(w, 1e-10f);
        e.x *= iw; e.y *= iw; e.z *= iw; e.w *= iw;
    }
}

__device__ __forceinline__ void writeout(float* __restrict__ out, size_t pos,
                                         const float4 e, const float4 lag) {
    float4 s;
    s.x = e.x - lag.x; s.y = e.y - lag.y; s.z = e.z - lag.z; s.w = e.w - lag.w;
    float4 ab, bl, bt;
    ab.x = (s.x >  15.0f) ? 1.0f : 0.0f;
    ab.y = (s.y >  15.0f) ? 1.0f : 0.0f;
    ab.z = (s.z >  15.0f) ? 1.0f : 0.0f;
    ab.w = (s.w >  15.0f) ? 1.0f : 0.0f;
    bl.x = (s.x < -15.0f) ? 1.0f : 0.0f;
    bl.y = (s.y < -15.0f) ? 1.0f : 0.0f;
    bl.z = (s.z < -15.0f) ? 1.0f : 0.0f;
    bl.w = (s.w < -15.0f) ? 1.0f : 0.0f;
    bt.x = 1.0f - ab.x - bl.x;
    bt.y = 1.0f - ab.y - bl.y;
    bt.z = 1.0f - ab.z - bl.z;
    bt.w = 1.0f - ab.w - bl.w;
    __stcs((float4*)(out +            pos), e);
    __stcs((float4*)(out + NTOT     + pos), s);
    __stcs((float4*)(out + 2 * NTOT + pos), ab);
    __stcs((float4*)(out + 3 * NTOT + pos), bl);
    __stcs((float4*)(out + 4 * NTOT + pos), bt);
}

__global__ void __launch_bounds__(128)
ema_slope_filter_kernel(const float* __restrict__ x, float* __restrict__ out) {
    int gtid = blockIdx.x * blockDim.x + threadIdx.x;
    int f4 = gtid & 15;                 // float4 index along F (f = f4*4)
    int b  = (gtid >> 4) & 63;
    int c  = gtid >> 10;                // chunk index 0..NC-1

    // x viewed as float4 rows: stride per t is F_DIM/4 = 16 float4
    const float4* xb = (const float4*)(x + (size_t)b * T_DIM * F_DIM) + f4;

    int t0 = c * CS;
    int te = t0 + CS;
    int ts = t0 - WU;
    if (ts < 0) ts = 0;                 // exact prefix for early chunks

    float4 e  = xb[(size_t)ts * 16];    // carry init: exact for ts==0, decayed-away otherwise
    float4 el = e;                      // 25-step delayed chain (holds ema[t-LAG])

    if (c == 0) {
        // t = 0: ema = x[0], lagged = 0
        float4 z = make_float4(0.f, 0.f, 0.f, 0.f);
        writeout(out, (size_t)b * T_DIM * F_DIM + f4 * 4, e, z);
    }

    // ---- warm-up: advance both chains, no writes ----
    #pragma unroll 4
    for (int t = ts + 1; t < t0; ++t) {
        float4 xt = xb[(size_t)t * 16];
        estep(e, xt, t);
        int tl = t - LAG;
        if (tl > ts) {
            float4 xl = xb[(size_t)tl * 16];   // L1 hit: loaded 25 steps ago
            estep(el, xl, tl);
        }
    }

    // ---- output phase ----
    int tstart = (t0 > ts + 1) ? t0 : ts + 1;   // ts+1 only for chunk 0
    #pragma unroll 2
    for (int t = tstart; t < te; ++t) {
        float4 xt = xb[(size_t)t * 16];
        estep(e, xt, t);
        int tl = t - LAG;
        if (tl > ts) {
            float4 xl = xb[(size_t)tl * 16];
            estep(el, xl, tl);
        }
        float4 lag = (tl >= 0) ? el : make_float4(0.f, 0.f, 0.f, 0.f);
        size_t pos = ((size_t)b * T_DIM + t) * F_DIM + f4 * 4;
        writeout(out, pos, e, lag);
    }
}

extern "C" void kernel_launch(void* const* d_in, const int* in_sizes, int n_in,
                              void* d_out, int out_size) {
    const float* x = (const float*)d_in[0];
    float* out = (float*)d_out;
    // 16 (f4) * 64 (b) * 32 (chunks) = 32768 threads
    int total = 16 * B_DIM * NC;
    ema_slope_filter_kernel<<<total / 128, 128>>>(x, out);
}

// round 3
// speedup vs baseline: 3.1979x; 3.1979x over previous
#include <cuda_runtime.h>

#define T_DIM 4096
#define B_DIM 64
#define F_DIM 64
#define CS    64               // output chunk size
#define WU    193              // warm-up steps (e: om^193~2e-7, el: om^168~1.5e-6)
#define NC    (T_DIM / CS)     // 64 chunks
#define LAG   25
#define NTOT  ((size_t)B_DIM * T_DIM * F_DIM)   // 16777216

#define ALPHA (2.0f / 26.0f)
#define OM    (24.0f / 26.0f)

__device__ __forceinline__ void estep(float4& e, const float4 xv, int t) {
    // e = (alpha * x_t + om * e_prev) / max(1 - om^(t+1), 1e-10)
    e.x = fmaf(OM, e.x, ALPHA * xv.x);
    e.y = fmaf(OM, e.y, ALPHA * xv.y);
    e.z = fmaf(OM, e.z, ALPHA * xv.z);
    e.w = fmaf(OM, e.w, ALPHA * xv.w);
    if (t < 192) {             // for t >= 166, om^(t+1) underflows below fp32 ulp of 1
        float w  = 1.0f - __powf(OM, (float)(t + 1));
        float iw = 1.0f / fmaxf(w, 1e-10f);
        e.x *= iw; e.y *= iw; e.z *= iw; e.w *= iw;
    }
}

__device__ __forceinline__ void writeout(float* __restrict__ out, size_t pos,
                                         const float4 e, const float4 lag) {
    float4 s;
    s.x = e.x - lag.x; s.y = e.y - lag.y; s.z = e.z - lag.z; s.w = e.w - lag.w;
    float4 ab, bl, bt;
    ab.x = (s.x >  15.0f) ? 1.0f : 0.0f;
    ab.y = (s.y >  15.0f) ? 1.0f : 0.0f;
    ab.z = (s.z >  15.0f) ? 1.0f : 0.0f;
    ab.w = (s.w >  15.0f) ? 1.0f : 0.0f;
    bl.x = (s.x < -15.0f) ? 1.0f : 0.0f;
    bl.y = (s.y < -15.0f) ? 1.0f : 0.0f;
    bl.z = (s.z < -15.0f) ? 1.0f : 0.0f;
    bl.w = (s.w < -15.0f) ? 1.0f : 0.0f;
    bt.x = 1.0f - ab.x - bl.x;
    bt.y = 1.0f - ab.y - bl.y;
    bt.z = 1.0f - ab.z - bl.z;
    bt.w = 1.0f - ab.w - bl.w;
    __stcs((float4*)(out +            pos), e);
    __stcs((float4*)(out + NTOT     + pos), s);
    __stcs((float4*)(out + 2 * NTOT + pos), ab);
    __stcs((float4*)(out + 3 * NTOT + pos), bl);
    __stcs((float4*)(out + 4 * NTOT + pos), bt);
}

__global__ void __launch_bounds__(128)
ema_slope_filter_kernel(const float* __restrict__ x, float* __restrict__ out) {
    int gtid = blockIdx.x * blockDim.x + threadIdx.x;
    int f4 = gtid & 15;                 // float4 index along F
    int b  = (gtid >> 4) & 63;
    int c  = gtid >> 10;                // chunk index 0..NC-1

    const float4* xb = (const float4*)(x + (size_t)b * T_DIM * F_DIM) + f4;
    size_t obase = (size_t)b * T_DIM * F_DIM + (size_t)f4 * 4;

    if (c == 0) {
        // exact prefix: t < LAG has lagged = 0; el chain starts stepping at tl = 1
        float4 e  = xb[0];
        float4 el = e;                  // el holds ema[t-LAG] at write time
        float4 z  = make_float4(0.f, 0.f, 0.f, 0.f);
        writeout(out, obase, e, z);
        for (int t = 1; t < LAG; ++t) {
            estep(e, xb[(size_t)t * 16], t);
            writeout(out, obase + (size_t)t * F_DIM, e, z);
        }
        for (int t = LAG; t < CS; ++t) {
            estep(e, xb[(size_t)t * 16], t);
            if (t > LAG)                // first el step at tl=1 (el seed IS ema[0])
                estep(el, xb[(size_t)(t - LAG) * 16], t - LAG);
            writeout(out, obase + (size_t)t * F_DIM, e, el);
        }
        return;
    }

    int t0 = c * CS;
    int te = t0 + CS;
    int ts = t0 - WU;
    if (ts < 0) ts = 0;                 // exact for c <= 3

    float4 e  = xb[(size_t)ts * 16];    // exact for ts==0, decayed-away otherwise
    float4 el = e;                      // 25-step delayed chain

    int t = ts + 1;

    // ---- phase A: first LAG warm-up steps, e-chain only (el first steps at tl=ts+1) ----
    {
        float4 xt[LAG];
        #pragma unroll
        for (int u = 0; u < LAG; ++u) xt[u] = xb[(size_t)(t + u) * 16];
        #pragma unroll
        for (int u = 0; u < LAG; ++u) estep(e, xt[u], t + u);
        t += LAG;
    }

    // ---- phase B: dual-chain warm-up, batched loads (MLP=16) ----
    for (; t + 8 <= t0; t += 8) {
        float4 xt[8], xl[8];
        #pragma unroll
        for (int u = 0; u < 8; ++u) xt[u] = xb[(size_t)(t + u) * 16];
        #pragma unroll
        for (int u = 0; u < 8; ++u) xl[u] = xb[(size_t)(t + u - LAG) * 16];
        #pragma unroll
        for (int u = 0; u < 8; ++u) {
            estep(e,  xt[u], t + u);
            estep(el, xl[u], t + u - LAG);
        }
    }
    for (; t < t0; ++t) {
        estep(e,  xb[(size_t)t * 16], t);
        estep(el, xb[(size_t)(t - LAG) * 16], t - LAG);
    }

    // ---- phase C: output, batched loads (MLP=8) + streaming stores ----
    for (; t < te; t += 4) {
        float4 xt[4], xl[4];
        #pragma unroll
        for (int u = 0; u < 4; ++u) xt[u] = xb[(size_t)(t + u) * 16];
        #pragma unroll
        for (int u = 0; u < 4; ++u) xl[u] = xb[(size_t)(t + u - LAG) * 16];
        #pragma unroll
        for (int u = 0; u < 4; ++u) {
            estep(e,  xt[u], t + u);
            estep(el, xl[u], t + u - LAG);
            writeout(out, obase + (size_t)(t + u) * F_DIM, e, el);
        }
    }
}

extern "C" void kernel_launch(void* const* d_in, const int* in_sizes, int n_in,
                              void* d_out, int out_size) {
    const float* x = (const float*)d_in[0];
    float* out = (float*)d_out;
    int total = 16 * B_DIM * NC;        // 65536 threads
    ema_slope_filter_kernel<<<total / 128, 128>>>(x, out);
}